// round 5
// baseline (speedup 1.0000x reference)
#include <cuda_runtime.h>
#include <math.h>

#define NG   256
#define HGT  512
#define WID  512
#define HW   (HGT * WID)
#define TB   128
#define PPB  (TB * 4)          // pixels per block (4 per thread, 2 f32x2 chains)
#define NBLK (HW / PPB)        // 512

// ---- constants -------------------------------------------------------------
constexpr double TWOPI_D  = 6.283185307179586476925286766559;
constexpr float  TWOPI_F  = (float)TWOPI_D;
constexpr float  RC1      = (float)TWOPI_D;
constexpr float  RC2      = (float)(TWOPI_D - (double)RC1);
constexpr float  INV2PI_F = (float)(1.0 / TWOPI_D);
constexpr double INV2PI_D = 1.0 / TWOPI_D;
constexpr float  L2E_F    = 1.4426950408889634f;   // == __expf's log2(e)

// ---- packed f32x2 helpers (each half bitwise identical to scalar op) --------
typedef unsigned long long F2;

__device__ __forceinline__ F2 f2pack(float lo, float hi) {
    F2 r; asm("mov.b64 %0, {%1, %2};" : "=l"(r) : "f"(lo), "f"(hi)); return r;
}
__device__ __forceinline__ void f2unpack(F2 v, float& lo, float& hi) {
    asm("mov.b64 {%0, %1}, %2;" : "=f"(lo), "=f"(hi) : "l"(v));
}
__device__ __forceinline__ F2 f2sub(F2 a, F2 b) {
    F2 r; asm("sub.rn.f32x2 %0, %1, %2;" : "=l"(r) : "l"(a), "l"(b)); return r;
}
__device__ __forceinline__ F2 f2mul(F2 a, F2 b) {
    F2 r; asm("mul.rn.f32x2 %0, %1, %2;" : "=l"(r) : "l"(a), "l"(b)); return r;
}
__device__ __forceinline__ F2 f2fma(F2 a, F2 b, F2 c) {
    F2 r; asm("fma.rn.f32x2 %0, %1, %2, %3;" : "=l"(r) : "l"(a), "l"(b), "l"(c)); return r;
}
__device__ __forceinline__ float ex2f(float x) {
    float r; asm("ex2.approx.f32 %0, %1;" : "=f"(r) : "f"(x)); return r;
}
__device__ __forceinline__ float sinaf(float x) {
    float r; asm("sin.approx.f32 %0, %1;" : "=f"(r) : "f"(x)); return r;
}
__device__ __forceinline__ float cosaf(float x) {
    float r; asm("cos.approx.f32 %0, %1;" : "=f"(r) : "f"(x)); return r;
}

// ---- device-global scratch ---------------------------------------------------
// 7 float4 per compacted gabor, every value DUPLICATED into an (x,x) pair:
//   [7n+0]=(uc,uc,vc,vc)  [7n+1]=(cr,cr,sr,sr)    [7n+2]=(i2s,i2s,i2g,i2g)
//   [7n+3]=(fr,fr,A0,A0)  [7n+4]=(A1,A1,A2,A2)    [7n+5]=(nB0,nB0,nB1,nB1)
//   [7n+6]=(nB2,nB2,0,0)
__device__ float4 g_k[NG * 7];
__device__ int    g_cnt;

__device__ __forceinline__ float clampf(float x, float lo, float hi) {
    return fminf(fmaxf(x, lo), hi);
}

// ---- prep kernel: clamp params, build coefficients, compact dead gabors -----
__global__ void prep_kernel(const float* __restrict__ u,
                            const float* __restrict__ v,
                            const float* __restrict__ theta,
                            const float* __restrict__ rsig,
                            const float* __restrict__ rfreq,
                            const float* __restrict__ gam,
                            const float* __restrict__ psi,
                            const float* __restrict__ amp) {
    int n = threadIdx.x;   // 256 threads, 1 block

    float uc = clampf(u[n], -1.f, 1.f);
    float vc = clampf(v[n], -1.f, 1.f);
    float th = clampf(theta[n], -2.f, 2.f) * TWOPI_F;
    float sr, cr;
    sincosf(th, &sr, &cr);

    float sg  = clampf(rsig[n], 1e-5f, 5.f);
    float gm  = clampf(gam[n],  1e-5f, 5.f);
    float i2s = -1.f / (2.f * sg * sg);
    float i2g = -1.f / (2.f * gm * gm);
    float fr  = TWOPI_F / expf(rfreq[n]);

    float A[3], nB[3];
    bool keep = false;
    #pragma unroll
    for (int c = 0; c < 3; ++c) {
        float a  = clampf(amp[3 * n + c], 0.f, 1.f);
        float ph = clampf(psi[3 * n + c], -1.f, 1.f) * TWOPI_F;
        float sp, cp;
        sincosf(ph, &sp, &cp);
        A[c]  =  a * cp;
        nB[c] = -a * sp;
        keep  = keep || (a > 0.f);
    }

    unsigned m = __ballot_sync(0xffffffffu, keep);
    __shared__ int wcnt[8];
    int wid = n >> 5, lid = n & 31;
    if (lid == 0) wcnt[wid] = __popc(m);
    __syncthreads();
    int basew = 0;
    for (int w = 0; w < wid; ++w) basew += wcnt[w];
    if (keep) {
        int p = basew + __popc(m & ((1u << lid) - 1u));
        g_k[7 * p + 0] = make_float4(uc,  uc,  vc,  vc);
        g_k[7 * p + 1] = make_float4(cr,  cr,  sr,  sr);
        g_k[7 * p + 2] = make_float4(i2s, i2s, i2g, i2g);
        g_k[7 * p + 3] = make_float4(fr,  fr,  A[0], A[0]);
        g_k[7 * p + 4] = make_float4(A[1], A[1], A[2], A[2]);
        g_k[7 * p + 5] = make_float4(nB[0], nB[0], nB[1], nB[1]);
        g_k[7 * p + 6] = make_float4(nB[2], nB[2], 0.f, 0.f);
    }
    __syncthreads();
    if (n == 0) {
        int tot = 0;
        #pragma unroll
        for (int w = 0; w < 8; ++w) tot += wcnt[w];
        g_cnt = tot;
    }
}

// ---- main kernel: 4 pixels per thread = 2 independent f32x2 chains -------------
__global__ void __launch_bounds__(TB)
gabor_kernel(const float* __restrict__ gx,
             const float* __restrict__ gy,
             float* __restrict__ out) {
    __shared__ ulonglong2 s_k[NG * 7];

    int cnt = g_cnt;
    {
        const ulonglong2* gk = reinterpret_cast<const ulonglong2*>(g_k);
        for (int i = threadIdx.x; i < 7 * cnt; i += TB) s_k[i] = gk[i];
    }
    __syncthreads();

    const int base = blockIdx.x * PPB + threadIdx.x;
    const int iA0 = base, iA1 = base + TB, iB0 = base + 2 * TB, iB1 = base + 3 * TB;

    const F2 pxA = f2pack(gx[iA0], gx[iA1]);
    const F2 pyA = f2pack(gy[iA0], gy[iA1]);
    const F2 pxB = f2pack(gx[iB0], gx[iB1]);
    const F2 pyB = f2pack(gy[iB0], gy[iB1]);

    const F2 ZERO  = 0ULL;
    const F2 L2EP  = f2pack(L2E_F, L2E_F);
    const F2 I2PIP = f2pack(INV2PI_F, INV2PI_F);
    const F2 RC1NP = f2pack(-RC1, -RC1);
    const F2 RC2NP = f2pack(-RC2, -RC2);

    F2 a0A = 0ULL, a1A = 0ULL, a2A = 0ULL;   // chain A accumulators
    F2 a0B = 0ULL, a1B = 0ULL, a2B = 0ULL;   // chain B accumulators

    for (int n = 0; n < cnt; ++n) {
        const ulonglong2* kn = &s_k[7 * n];
        ulonglong2 q0 = kn[0];   // (ucP, vcP)
        ulonglong2 q1 = kn[1];   // (crP, srP)
        ulonglong2 q2 = kn[2];   // (i2sP, i2gP)

        // chain A — bitwise identical per half to the scalar reference path
        F2 dxA = f2sub(pxA, q0.x);
        F2 dyA = f2sub(pyA, q0.y);
        F2 xrA = f2fma(dxA, q1.x, f2mul(dyA, q1.y));
        F2 yrA = f2fma(dyA, q1.x, f2sub(ZERO, f2mul(dxA, q1.y)));
        F2 argA = f2fma(f2mul(yrA, yrA), q2.y, f2mul(f2mul(xrA, xrA), q2.x));

        // chain B (independent — hides latency of chain A)
        F2 dxB = f2sub(pxB, q0.x);
        F2 dyB = f2sub(pyB, q0.y);
        F2 xrB = f2fma(dxB, q1.x, f2mul(dyB, q1.y));
        F2 yrB = f2fma(dyB, q1.x, f2sub(ZERO, f2mul(dxB, q1.y)));
        F2 argB = f2fma(f2mul(yrB, yrB), q2.y, f2mul(f2mul(xrB, xrB), q2.x));

        float aa0, aa1, ab0, ab1;
        f2unpack(argA, aa0, aa1);
        f2unpack(argB, ab0, ab1);
        float amax = fmaxf(fmaxf(aa0, aa1), fmaxf(ab0, ab1));
        // warp-level skip: dropped contributions < e^-17 each, total < ~1e-5
        if (!__any_sync(0xffffffffu, amax > -17.0f)) continue;

        ulonglong2 q3 = kn[3];   // (frP, A0P)
        ulonglong2 q4 = kn[4];   // (A1P, A2P)
        ulonglong2 q5 = kn[5];   // (nB0P, nB1P)
        ulonglong2 q6 = kn[6];   // (nB2P, --)

        // ---- chain A active path ----
        {
            float e0, e1;
            f2unpack(f2mul(argA, L2EP), e0, e1);
            float g0 = ex2f(e0), g1 = ex2f(e1);

            F2 fxP = f2mul(q3.x, xrA);
            float fx0, fx1;
            f2unpack(fxP, fx0, fx1);

            float k0raw, k1raw;
            f2unpack(f2mul(fxP, I2PIP), k0raw, k1raw);
            F2 kP = f2pack(rintf(k0raw), rintf(k1raw));
            F2 rP = f2fma(kP, RC1NP, fxP);
            rP = f2fma(kP, RC2NP, rP);
            float r0, r1;
            f2unpack(rP, r0, r1);

            if (fabsf(fx0) >= 1.0e7f) {
                double xd = (double)fx0, q = rint(xd * INV2PI_D);
                r0 = (float)fma(q, -TWOPI_D, xd);
            }
            if (fabsf(fx1) >= 1.0e7f) {
                double xd = (double)fx1, q = rint(xd * INV2PI_D);
                r1 = (float)fma(q, -TWOPI_D, xd);
            }

            float s0 = sinaf(r0), c0 = cosaf(r0);
            float s1 = sinaf(r1), c1 = cosaf(r1);

            F2 gcP = f2pack(g0 * c0, g1 * c1);
            F2 gsP = f2pack(g0 * s0, g1 * s1);

            a0A = f2fma(gcP, q3.y, f2fma(gsP, q5.x, a0A));
            a1A = f2fma(gcP, q4.x, f2fma(gsP, q5.y, a1A));
            a2A = f2fma(gcP, q4.y, f2fma(gsP, q6.x, a2A));
        }

        // ---- chain B active path ----
        {
            float e0, e1;
            f2unpack(f2mul(argB, L2EP), e0, e1);
            float g0 = ex2f(e0), g1 = ex2f(e1);

            F2 fxP = f2mul(q3.x, xrB);
            float fx0, fx1;
            f2unpack(fxP, fx0, fx1);

            float k0raw, k1raw;
            f2unpack(f2mul(fxP, I2PIP), k0raw, k1raw);
            F2 kP = f2pack(rintf(k0raw), rintf(k1raw));
            F2 rP = f2fma(kP, RC1NP, fxP);
            rP = f2fma(kP, RC2NP, rP);
            float r0, r1;
            f2unpack(rP, r0, r1);

            if (fabsf(fx0) >= 1.0e7f) {
                double xd = (double)fx0, q = rint(xd * INV2PI_D);
                r0 = (float)fma(q, -TWOPI_D, xd);
            }
            if (fabsf(fx1) >= 1.0e7f) {
                double xd = (double)fx1, q = rint(xd * INV2PI_D);
                r1 = (float)fma(q, -TWOPI_D, xd);
            }

            float s0 = sinaf(r0), c0 = cosaf(r0);
            float s1 = sinaf(r1), c1 = cosaf(r1);

            F2 gcP = f2pack(g0 * c0, g1 * c1);
            F2 gsP = f2pack(g0 * s0, g1 * s1);

            a0B = f2fma(gcP, q3.y, f2fma(gsP, q5.x, a0B));
            a1B = f2fma(gcP, q4.x, f2fma(gsP, q5.y, a1B));
            a2B = f2fma(gcP, q4.y, f2fma(gsP, q6.x, a2B));
        }
    }

    float v0, v1;
    f2unpack(a0A, v0, v1);
    out[iA0] = clampf(v0, -1.f, 1.f);  out[iA1] = clampf(v1, -1.f, 1.f);
    f2unpack(a0B, v0, v1);
    out[iB0] = clampf(v0, -1.f, 1.f);  out[iB1] = clampf(v1, -1.f, 1.f);
    f2unpack(a1A, v0, v1);
    out[HW + iA0] = clampf(v0, -1.f, 1.f);  out[HW + iA1] = clampf(v1, -1.f, 1.f);
    f2unpack(a1B, v0, v1);
    out[HW + iB0] = clampf(v0, -1.f, 1.f);  out[HW + iB1] = clampf(v1, -1.f, 1.f);
    f2unpack(a2A, v0, v1);
    out[2 * HW + iA0] = clampf(v0, -1.f, 1.f);  out[2 * HW + iA1] = clampf(v1, -1.f, 1.f);
    f2unpack(a2B, v0, v1);
    out[2 * HW + iB0] = clampf(v0, -1.f, 1.f);  out[2 * HW + iB1] = clampf(v1, -1.f, 1.f);
}

// ---- launch ----------------------------------------------------------------------
extern "C" void kernel_launch(void* const* d_in, const int* in_sizes, int n_in,
                              void* d_out, int out_size) {
    const float* gx    = (const float*)d_in[0];
    const float* gy    = (const float*)d_in[1];
    const float* u     = (const float*)d_in[2];
    const float* v     = (const float*)d_in[3];
    const float* theta = (const float*)d_in[4];
    const float* rsig  = (const float*)d_in[5];
    const float* rfreq = (const float*)d_in[6];
    const float* gam   = (const float*)d_in[7];
    const float* psi   = (const float*)d_in[8];
    const float* amp   = (const float*)d_in[9];
    float* out = (float*)d_out;

    prep_kernel<<<1, NG>>>(u, v, theta, rsig, rfreq, gam, psi, amp);
    gabor_kernel<<<NBLK, TB>>>(gx, gy, out);
}

// round 6
// speedup vs baseline: 1.0827x; 1.0827x over previous
#include <cuda_runtime.h>
#include <math.h>

#define NG   256
#define HGT  512
#define WID  512
#define HW   (HGT * WID)
#define TB   256
#define HTH  128               // threads per gabor-half
#define PPB  256               // pixels per block (2 per pixel-thread)
#define NBLK (HW / PPB)        // 1024

// ---- constants -------------------------------------------------------------
constexpr double TWOPI_D  = 6.283185307179586476925286766559;
constexpr float  TWOPI_F  = (float)TWOPI_D;
constexpr float  RC1      = (float)TWOPI_D;
constexpr float  RC2      = (float)(TWOPI_D - (double)RC1);
constexpr float  INV2PI_F = (float)(1.0 / TWOPI_D);
constexpr double INV2PI_D = 1.0 / TWOPI_D;
constexpr float  L2E_F    = 1.4426950408889634f;   // == __expf's log2(e)

// ---- packed f32x2 helpers (each half bitwise identical to scalar op) --------
typedef unsigned long long F2;

__device__ __forceinline__ F2 f2pack(float lo, float hi) {
    F2 r; asm("mov.b64 %0, {%1, %2};" : "=l"(r) : "f"(lo), "f"(hi)); return r;
}
__device__ __forceinline__ void f2unpack(F2 v, float& lo, float& hi) {
    asm("mov.b64 {%0, %1}, %2;" : "=f"(lo), "=f"(hi) : "l"(v));
}
__device__ __forceinline__ F2 f2add(F2 a, F2 b) {
    F2 r; asm("add.rn.f32x2 %0, %1, %2;" : "=l"(r) : "l"(a), "l"(b)); return r;
}
__device__ __forceinline__ F2 f2sub(F2 a, F2 b) {
    F2 r; asm("sub.rn.f32x2 %0, %1, %2;" : "=l"(r) : "l"(a), "l"(b)); return r;
}
__device__ __forceinline__ F2 f2mul(F2 a, F2 b) {
    F2 r; asm("mul.rn.f32x2 %0, %1, %2;" : "=l"(r) : "l"(a), "l"(b)); return r;
}
__device__ __forceinline__ F2 f2fma(F2 a, F2 b, F2 c) {
    F2 r; asm("fma.rn.f32x2 %0, %1, %2, %3;" : "=l"(r) : "l"(a), "l"(b), "l"(c)); return r;
}
__device__ __forceinline__ float ex2f(float x) {
    float r; asm("ex2.approx.f32 %0, %1;" : "=f"(r) : "f"(x)); return r;
}
__device__ __forceinline__ float sinaf(float x) {
    float r; asm("sin.approx.f32 %0, %1;" : "=f"(r) : "f"(x)); return r;
}
__device__ __forceinline__ float cosaf(float x) {
    float r; asm("cos.approx.f32 %0, %1;" : "=f"(r) : "f"(x)); return r;
}

// ---- device-global scratch ---------------------------------------------------
// 7 float4 per compacted gabor, every value DUPLICATED into an (x,x) pair:
//   [7n+0]=(uc,uc,vc,vc)  [7n+1]=(cr,cr,sr,sr)    [7n+2]=(i2s,i2s,i2g,i2g)
//   [7n+3]=(fr,fr,A0,A0)  [7n+4]=(A1,A1,A2,A2)    [7n+5]=(nB0,nB0,nB1,nB1)
//   [7n+6]=(nB2,nB2,0,0)
__device__ float4 g_k[NG * 7];
__device__ int    g_cnt;

__device__ __forceinline__ float clampf(float x, float lo, float hi) {
    return fminf(fmaxf(x, lo), hi);
}

// ---- prep kernel: clamp params, build coefficients, compact dead gabors -----
__global__ void prep_kernel(const float* __restrict__ u,
                            const float* __restrict__ v,
                            const float* __restrict__ theta,
                            const float* __restrict__ rsig,
                            const float* __restrict__ rfreq,
                            const float* __restrict__ gam,
                            const float* __restrict__ psi,
                            const float* __restrict__ amp) {
    int n = threadIdx.x;   // 256 threads, 1 block

    float uc = clampf(u[n], -1.f, 1.f);
    float vc = clampf(v[n], -1.f, 1.f);
    float th = clampf(theta[n], -2.f, 2.f) * TWOPI_F;
    float sr, cr;
    sincosf(th, &sr, &cr);

    float sg  = clampf(rsig[n], 1e-5f, 5.f);
    float gm  = clampf(gam[n],  1e-5f, 5.f);
    float i2s = -1.f / (2.f * sg * sg);
    float i2g = -1.f / (2.f * gm * gm);
    float fr  = TWOPI_F / expf(rfreq[n]);

    float A[3], nB[3];
    bool keep = false;
    #pragma unroll
    for (int c = 0; c < 3; ++c) {
        float a  = clampf(amp[3 * n + c], 0.f, 1.f);
        float ph = clampf(psi[3 * n + c], -1.f, 1.f) * TWOPI_F;
        float sp, cp;
        sincosf(ph, &sp, &cp);
        A[c]  =  a * cp;
        nB[c] = -a * sp;
        keep  = keep || (a > 0.f);
    }

    unsigned m = __ballot_sync(0xffffffffu, keep);
    __shared__ int wcnt[8];
    int wid = n >> 5, lid = n & 31;
    if (lid == 0) wcnt[wid] = __popc(m);
    __syncthreads();
    int basew = 0;
    for (int w = 0; w < wid; ++w) basew += wcnt[w];
    if (keep) {
        int p = basew + __popc(m & ((1u << lid) - 1u));
        g_k[7 * p + 0] = make_float4(uc,  uc,  vc,  vc);
        g_k[7 * p + 1] = make_float4(cr,  cr,  sr,  sr);
        g_k[7 * p + 2] = make_float4(i2s, i2s, i2g, i2g);
        g_k[7 * p + 3] = make_float4(fr,  fr,  A[0], A[0]);
        g_k[7 * p + 4] = make_float4(A[1], A[1], A[2], A[2]);
        g_k[7 * p + 5] = make_float4(nB[0], nB[0], nB[1], nB[1]);
        g_k[7 * p + 6] = make_float4(nB[2], nB[2], 0.f, 0.f);
    }
    __syncthreads();
    if (n == 0) {
        int tot = 0;
        #pragma unroll
        for (int w = 0; w < 8; ++w) tot += wcnt[w];
        g_cnt = tot;
    }
}

// ---- main kernel: gabor loop split across two warpgroups, smem reduction -------
__global__ void __launch_bounds__(TB)
gabor_kernel(const float* __restrict__ gx,
             const float* __restrict__ gy,
             float* __restrict__ out) {
    __shared__ ulonglong2 s_k[NG * 7];     // 28 KB packed params
    __shared__ F2 s_part[HTH * 3];         // 3 KB high-half partials

    int cnt = g_cnt;
    {
        const ulonglong2* gk = reinterpret_cast<const ulonglong2*>(g_k);
        for (int i = threadIdx.x; i < 7 * cnt; i += TB) s_k[i] = gk[i];
    }
    __syncthreads();

    const int half = threadIdx.x >> 7;       // 0: warps 0-3, 1: warps 4-7
    const int pt   = threadIdx.x & (HTH - 1);
    const int base = blockIdx.x * PPB;
    const int idx0 = base + pt;
    const int idx1 = base + HTH + pt;

    const F2 pxP = f2pack(gx[idx0], gx[idx1]);
    const F2 pyP = f2pack(gy[idx0], gy[idx1]);

    const F2 ZERO  = 0ULL;
    const F2 L2EP  = f2pack(L2E_F, L2E_F);
    const F2 I2PIP = f2pack(INV2PI_F, INV2PI_F);
    const F2 RC1NP = f2pack(-RC1, -RC1);
    const F2 RC2NP = f2pack(-RC2, -RC2);

    F2 acc0 = 0ULL, acc1 = 0ULL, acc2 = 0ULL;

    const int cnt2 = (cnt + 1) >> 1;
    const int n0 = half ? cnt2 : 0;
    const int n1 = half ? cnt  : cnt2;

    for (int n = n0; n < n1; ++n) {
        const ulonglong2* kn = &s_k[7 * n];
        ulonglong2 q0 = kn[0];   // (ucP, vcP)
        ulonglong2 q1 = kn[1];   // (crP, srP)
        ulonglong2 q2 = kn[2];   // (i2sP, i2gP)

        // bitwise-per-half identical to the scalar reference path
        F2 dx = f2sub(pxP, q0.x);
        F2 dy = f2sub(pyP, q0.y);
        F2 xr = f2fma(dx, q1.x, f2mul(dy, q1.y));
        F2 yr = f2fma(dy, q1.x, f2sub(ZERO, f2mul(dx, q1.y)));
        F2 arg = f2fma(f2mul(yr, yr), q2.y, f2mul(f2mul(xr, xr), q2.x));

        float a0, a1;
        f2unpack(arg, a0, a1);
        // warp-level skip: dropped contributions < e^-17 each, total < ~1e-5
        if (!__any_sync(0xffffffffu, fmaxf(a0, a1) > -17.0f)) continue;

        ulonglong2 q3 = kn[3];   // (frP, A0P)
        ulonglong2 q4 = kn[4];   // (A1P, A2P)
        ulonglong2 q5 = kn[5];   // (nB0P, nB1P)
        ulonglong2 q6 = kn[6];   // (nB2P, --)

        // gaussian: exactly __expf(arg) per half
        float e0, e1;
        f2unpack(f2mul(arg, L2EP), e0, e1);
        float g0 = ex2f(e0), g1 = ex2f(e1);

        // carrier phase: fx = freq*xr (frozen expression tree)
        F2 fxP = f2mul(q3.x, xr);
        float fx0, fx1;
        f2unpack(fxP, fx0, fx1);

        // 2-term FMA Cody-Waite reduction to [-pi, pi]
        float k0raw, k1raw;
        f2unpack(f2mul(fxP, I2PIP), k0raw, k1raw);
        F2 kP = f2pack(rintf(k0raw), rintf(k1raw));
        F2 rP = f2fma(kP, RC1NP, fxP);
        rP = f2fma(kP, RC2NP, rP);
        float r0, r1;
        f2unpack(rP, r0, r1);

        // rare extreme-frequency gabor: fp64 reduction per half
        if (fabsf(fx0) >= 1.0e7f) {
            double xd = (double)fx0, q = rint(xd * INV2PI_D);
            r0 = (float)fma(q, -TWOPI_D, xd);
        }
        if (fabsf(fx1) >= 1.0e7f) {
            double xd = (double)fx1, q = rint(xd * INV2PI_D);
            r1 = (float)fma(q, -TWOPI_D, xd);
        }

        float s0 = sinaf(r0), c0 = cosaf(r0);
        float s1 = sinaf(r1), c1 = cosaf(r1);

        F2 gcP = f2pack(g0 * c0, g1 * c1);
        F2 gsP = f2pack(g0 * s0, g1 * s1);

        acc0 = f2fma(gcP, q3.y, f2fma(gsP, q5.x, acc0));
        acc1 = f2fma(gcP, q4.x, f2fma(gsP, q5.y, acc1));
        acc2 = f2fma(gcP, q4.y, f2fma(gsP, q6.x, acc2));
    }

    // combine halves: high warpgroup publishes, low warpgroup reduces + stores
    if (half) {
        s_part[pt]           = acc0;
        s_part[pt + HTH]     = acc1;
        s_part[pt + 2 * HTH] = acc2;
    }
    __syncthreads();
    if (!half) {
        acc0 = f2add(acc0, s_part[pt]);
        acc1 = f2add(acc1, s_part[pt + HTH]);
        acc2 = f2add(acc2, s_part[pt + 2 * HTH]);

        float v0, v1;
        f2unpack(acc0, v0, v1);
        out[idx0] = clampf(v0, -1.f, 1.f);
        out[idx1] = clampf(v1, -1.f, 1.f);
        f2unpack(acc1, v0, v1);
        out[HW + idx0] = clampf(v0, -1.f, 1.f);
        out[HW + idx1] = clampf(v1, -1.f, 1.f);
        f2unpack(acc2, v0, v1);
        out[2 * HW + idx0] = clampf(v0, -1.f, 1.f);
        out[2 * HW + idx1] = clampf(v1, -1.f, 1.f);
    }
}

// ---- launch ----------------------------------------------------------------------
extern "C" void kernel_launch(void* const* d_in, const int* in_sizes, int n_in,
                              void* d_out, int out_size) {
    const float* gx    = (const float*)d_in[0];
    const float* gy    = (const float*)d_in[1];
    const float* u     = (const float*)d_in[2];
    const float* v     = (const float*)d_in[3];
    const float* theta = (const float*)d_in[4];
    const float* rsig  = (const float*)d_in[5];
    const float* rfreq = (const float*)d_in[6];
    const float* gam   = (const float*)d_in[7];
    const float* psi   = (const float*)d_in[8];
    const float* amp   = (const float*)d_in[9];
    float* out = (float*)d_out;

    prep_kernel<<<1, NG>>>(u, v, theta, rsig, rfreq, gam, psi, amp);
    gabor_kernel<<<NBLK, TB>>>(gx, gy, out);
}